// round 12
// baseline (speedup 1.0000x reference)
#include <cuda_runtime.h>
#include <cuda_fp16.h>
#include <cstdint>

#define Bn 16

// A staging: [slot4][px row 0..129][ci 64, pitch 72 halfs = 144B]
#define APITCH 144
#define ASLOT  (130 * APITCH)          // 18720
#define A_TOTAL (4 * ASLOT)            // 74880
#define BS_OFF A_TOTAL                 // 74880
#define BBUF   9216                    // one tap: 64 ci x 144B
#define BIAS_OFF (BS_OFF + 2 * BBUF)   // 93312
#define SMEM_TOTAL (BIAS_OFF + 256)    // 93568

// weights: per (b,tap): [ci64][co pitch 72] fp16 = 4608 elems
__device__ __half g_w[Bn * 9 * 4608];

__device__ __forceinline__ float lrelu(float v) { return v > 0.f ? v : 0.01f * v; }

__device__ __forceinline__ uint32_t smem_u32(const void* p) {
    uint32_t a;
    asm("{ .reg .u64 t; cvta.to.shared.u64 t, %1; cvt.u32.u64 %0, t; }" : "=r"(a) : "l"(p));
    return a;
}
__device__ __forceinline__ void ldsm4(uint32_t* r, uint32_t a) {
    asm volatile("ldmatrix.sync.aligned.m8n8.x4.shared.b16 {%0,%1,%2,%3},[%4];"
        : "=r"(r[0]), "=r"(r[1]), "=r"(r[2]), "=r"(r[3]) : "r"(a));
}
__device__ __forceinline__ void ldsm4t(uint32_t* r, uint32_t a) {
    asm volatile("ldmatrix.sync.aligned.m8n8.x4.trans.shared.b16 {%0,%1,%2,%3},[%4];"
        : "=r"(r[0]), "=r"(r[1]), "=r"(r[2]), "=r"(r[3]) : "r"(a));
}
__device__ __forceinline__ void mma16(float* c, const uint32_t* a, uint32_t b0, uint32_t b1) {
    asm volatile("mma.sync.aligned.m16n8k16.row.col.f32.f16.f16.f32 "
        "{%0,%1,%2,%3},{%4,%5,%6,%7},{%8,%9},{%0,%1,%2,%3};"
        : "+f"(c[0]), "+f"(c[1]), "+f"(c[2]), "+f"(c[3])
        : "r"(a[0]), "r"(a[1]), "r"(a[2]), "r"(a[3]), "r"(b0), "r"(b1));
}
__device__ __forceinline__ void cpa16(uint32_t dst, const void* src) {
    asm volatile("cp.async.cg.shared.global [%0],[%1],16;" :: "r"(dst), "l"(src));
}
#define CP_COMMIT() asm volatile("cp.async.commit_group;" ::: "memory")
#define CP_WAIT0()  asm volatile("cp.async.wait_group 0;" ::: "memory")

__device__ __forceinline__ uint32_t h2(float a, float b) {
    __half2 v = __floats2half2_rn(a, b);
    return *reinterpret_cast<uint32_t*>(&v);
}

// ---------------------------------------------------------------------------
// wgen: full hypernet -> g_w (fp16). grid (64 co, 16 b), 256 thr.
// ---------------------------------------------------------------------------
__global__ void wgen_kernel(const float* __restrict__ h,
                            const float* __restrict__ fc_w, const float* __restrict__ fc_b,
                            const float* __restrict__ w1, const float* __restrict__ b1,
                            const float* __restrict__ w2, const float* __restrict__ b2,
                            const float* __restrict__ w3, const float* __restrict__ b3) {
    int co = blockIdx.x, b = blockIdx.y, tid = threadIdx.x;
    __shared__ float k1[144], k2[288], k3[288], w3s[64 * 32];

    if (tid < 144) {
        float s = fc_b[tid];
#pragma unroll
        for (int q = 0; q < 8; q++) s += h[b * 8 + q] * fc_w[tid * 8 + q];
        k1[tid] = lrelu(s);
    }
    __syncthreads();
    for (int i = tid; i < 288; i += 256) {
        int o = i / 9, t = i % 9;
        float s = b1[o];
#pragma unroll
        for (int c = 0; c < 16; c++) s += w1[o * 16 + c] * k1[c * 9 + t];
        k2[i] = lrelu(s);
    }
    __syncthreads();
    for (int i = tid; i < 288; i += 256) {
        int o = i / 9, t = i % 9;
        float s = b2[o];
#pragma unroll
        for (int c = 0; c < 32; c++) s += w2[o * 32 + c] * k2[c * 9 + t];
        k3[i] = lrelu(s);
    }
    for (int i = tid; i < 2048; i += 256) w3s[i] = w3[(co * 64) * 32 + i];
    __syncthreads();

    for (int e = tid; e < 576; e += 256) {
        int ci = e / 9, t = e % 9;
        float s = b3[co * 64 + ci];
#pragma unroll
        for (int c = 0; c < 32; c++) s += w3s[ci * 32 + c] * k3[c * 9 + t];
        g_w[(size_t)(b * 9 + t) * 4608 + (size_t)ci * 72 + co] = __float2half(s);
    }
}

// ---------------------------------------------------------------------------
// conv: implicit GEMM via mma.sync fp16 (single term). grid (64 row-pairs, 16 b),
// 256 thr, 2 CTAs/SM. A staged DIRECTLY from f32 x via register transpose:
// lane = (c4 = lane>>2, pq = lane&3): 8 float4 loads from 8 ci-planes at one
// px-quad -> 16 cvt.f16x2 -> 4 STS.128 into A[px][ci].
// ---------------------------------------------------------------------------
__global__ void __launch_bounds__(256, 2)
conv_kernel(const float* __restrict__ x, const float* __restrict__ bias,
            float* __restrict__ y) {
    extern __shared__ char smem[];
    uint32_t xs_sh = smem_u32(smem);
    uint32_t bs_sh = xs_sh + BS_OFF;
    int tid = threadIdx.x, lane = tid & 31, wid = tid >> 5;
    int y0 = blockIdx.x * 2, b = blockIdx.y;

    // B tap0 cp.async (576 x 16B)
    {
        const char* g0 = (const char*)(g_w + (size_t)(b * 9) * 4608);
        for (int i = tid; i < 576; i += 256) cpa16(bs_sh + i * 16, g0 + i * 16);
        CP_COMMIT();
    }

    if (tid < 64) ((float*)(smem + BIAS_OFF))[tid] = bias[tid];
    // zero halo rows (px -1 and px 128) for all slots
    uint4 z4 = make_uint4(0, 0, 0, 0);
    if (tid < 72) {
        int sl = tid / 18, rr = (tid / 9) & 1, ck = tid % 9;
        *(uint4*)(smem + sl * ASLOT + (rr ? 129 * APITCH : 0) + ck * 16) = z4;
    }
    // zero invalid slots (edge row-pairs)
    if (y0 == 0)
        for (int i = tid; i < 1170; i += 256) *(uint4*)(smem + i * 16) = z4;
    if (y0 == 126)
        for (int i = tid; i < 1170; i += 256) *(uint4*)(smem + 3 * ASLOT + i * 16) = z4;

    // ---- A staging: register transpose from f32 x ----
    // warp w: slot sl = w>>1, px half = (w&1)*64; 4 strips of 16 px.
    {
        int sl = wid >> 1;
        int yy = y0 - 1 + sl;
        if ((unsigned)yy <= 127u) {
            int c4 = lane >> 2, pq = lane & 3;
            const float* xb = x + (((size_t)(b * 64 + c4 * 8)) * 128 + yy) * 128;
#pragma unroll
            for (int it = 0; it < 4; it++) {
                int pxq = (wid & 1) * 64 + it * 16 + pq * 4;
                float4 v[8];
#pragma unroll
                for (int j = 0; j < 8; j++)
                    v[j] = *reinterpret_cast<const float4*>(xb + (size_t)j * 16384 + pxq);
                char* dst = smem + sl * ASLOT + (pxq + 1) * APITCH + c4 * 16;
#pragma unroll
                for (int k = 0; k < 4; k++) {
                    float f0 = k == 0 ? v[0].x : k == 1 ? v[0].y : k == 2 ? v[0].z : v[0].w;
                    float f1 = k == 0 ? v[1].x : k == 1 ? v[1].y : k == 2 ? v[1].z : v[1].w;
                    float f2 = k == 0 ? v[2].x : k == 1 ? v[2].y : k == 2 ? v[2].z : v[2].w;
                    float f3 = k == 0 ? v[3].x : k == 1 ? v[3].y : k == 2 ? v[3].z : v[3].w;
                    float f4 = k == 0 ? v[4].x : k == 1 ? v[4].y : k == 2 ? v[4].z : v[4].w;
                    float f5 = k == 0 ? v[5].x : k == 1 ? v[5].y : k == 2 ? v[5].z : v[5].w;
                    float f6 = k == 0 ? v[6].x : k == 1 ? v[6].y : k == 2 ? v[6].z : v[6].w;
                    float f7 = k == 0 ? v[7].x : k == 1 ? v[7].y : k == 2 ? v[7].z : v[7].w;
                    uint4 u = make_uint4(h2(f0, f1), h2(f2, f3), h2(f4, f5), h2(f6, f7));
                    *reinterpret_cast<uint4*>(dst + k * APITCH) = u;
                }
            }
        }
    }

    CP_WAIT0();
    __syncthreads();

    int r = wid >> 2;                 // output row within pair
    int wpx = (wid & 3) * 32;         // warp's px base
    uint32_t lane_off = (uint32_t)((((lane >> 3) & 1) * 8 + (lane & 7)) * 144 + (lane >> 4) * 16);

    float acc[64];
#pragma unroll
    for (int i = 0; i < 64; i++) acc[i] = 0.f;

    for (int t = 0; t < 9; t++) {
        int buf = t & 1;
        if (t < 8) {
            const char* gt = (const char*)(g_w + (size_t)(b * 9 + t + 1) * 4608);
            uint32_t db = bs_sh + (buf ^ 1) * BBUF;
            for (int i = tid; i < 576; i += 256) cpa16(db + i * 16, gt + i * 16);
            CP_COMMIT();
        }
        int dy = t / 3 - 1, dx = t % 3 - 1;
        int slot = 1 + dy + r;
        uint32_t abase = xs_sh + slot * ASLOT + (uint32_t)(wpx + 1 + dx) * APITCH + lane_off;
        uint32_t bbase = bs_sh + buf * BBUF + lane_off;
#pragma unroll
        for (int kc = 0; kc < 4; kc++) {
            uint32_t a[2][4];
            ldsm4(a[0], abase + kc * 32);
            ldsm4(a[1], abase + kc * 32 + 2304);
            uint32_t bh[4][4];
#pragma unroll
            for (int np = 0; np < 4; np++)
                ldsm4t(bh[np], bbase + kc * 2304 + np * 32);
#pragma unroll
            for (int np = 0; np < 4; np++)
#pragma unroll
                for (int mt = 0; mt < 2; mt++) {
                    float* A0 = acc + ((mt * 4 + np) * 2 + 0) * 4;
                    float* A1 = acc + ((mt * 4 + np) * 2 + 1) * 4;
                    mma16(A0, a[mt], bh[np][0], bh[np][1]);
                    mma16(A1, a[mt], bh[np][2], bh[np][3]);
                }
        }
        if (t < 8) { CP_WAIT0(); __syncthreads(); }
    }

    // epilogue: regs -> smem transpose [co][px pitch132] -> coalesced STG
    __syncthreads();
    {
        float* dsm = (float*)(smem + (r ? 33792 : 0));
        int g = lane >> 2, tq = lane & 3;
#pragma unroll
        for (int mt = 0; mt < 2; mt++)
#pragma unroll
            for (int np = 0; np < 4; np++)
#pragma unroll
                for (int s = 0; s < 2; s++) {
                    float* a4 = acc + ((mt * 4 + np) * 2 + s) * 4;
                    int co = np * 16 + s * 8 + 2 * tq;
                    int px = wpx + mt * 16 + g;
                    dsm[co * 132 + px] = a4[0];
                    dsm[(co + 1) * 132 + px] = a4[1];
                    dsm[co * 132 + px + 8] = a4[2];
                    dsm[(co + 1) * 132 + px + 8] = a4[3];
                }
    }
    __syncthreads();
    for (int i = tid; i < 4096; i += 256) {
        int rr = i >> 11, co = (i >> 5) & 63, q = i & 31;
        float4 v = *(float4*)((float*)(smem + (rr ? 33792 : 0)) + co * 132 + q * 4);
        float bb = ((float*)(smem + BIAS_OFF))[co];
        v.x += bb; v.y += bb; v.z += bb; v.w += bb;
        *(float4*)(y + (((size_t)(b * 64 + co)) * 128 + y0 + rr) * 128 + q * 4) = v;
    }
}

// ---------------------------------------------------------------------------
extern "C" void kernel_launch(void* const* d_in, const int* in_sizes, int n_in,
                              void* d_out, int out_size) {
    const float* x    = (const float*)d_in[0];
    const float* h    = (const float*)d_in[1];
    const float* fc_w = (const float*)d_in[2];
    const float* fc_b = (const float*)d_in[3];
    const float* w1   = (const float*)d_in[4];
    const float* b1   = (const float*)d_in[5];
    const float* w2   = (const float*)d_in[6];
    const float* b2   = (const float*)d_in[7];
    const float* w3   = (const float*)d_in[8];
    const float* b3   = (const float*)d_in[9];
    const float* bias = (const float*)d_in[10];
    float* y = (float*)d_out;

    cudaFuncSetAttribute(conv_kernel, cudaFuncAttributeMaxDynamicSharedMemorySize,
                         SMEM_TOTAL);

    wgen_kernel<<<dim3(64, 16), 256>>>(h, fc_w, fc_b, w1, b1, w2, b2, w3, b3);
    conv_kernel<<<dim3(64, 16), 256, SMEM_TOTAL>>>(x, bias, y);
}

// round 14
// speedup vs baseline: 1.4329x; 1.4329x over previous
#include <cuda_runtime.h>
#include <cuda_fp16.h>
#include <cstdint>

#define Bn 16

// A staging: [slot4][px row 0..129][ci 64, pitch 72 halfs = 144B]
#define APITCH 144
#define ASLOT  (130 * APITCH)          // 18720
#define A_TOTAL (4 * ASLOT)            // 74880
#define BS_OFF A_TOTAL                 // 74880
#define BBUF   9216                    // one tap: 64 ci x 144B
#define BIAS_OFF (BS_OFF + 2 * BBUF)   // 93312
#define SMEM_TOTAL (BIAS_OFF + 256)    // 93568

// weights: per (b,tap): [ci64][co pitch 72] fp16 = 4608 elems
__device__ __half g_w[Bn * 9 * 4608];
// x pre-converted: [b][y][px][ci64] fp16
__device__ __half g_xh[(size_t)Bn * 128 * 128 * 64];

__device__ __forceinline__ float lrelu(float v) { return v > 0.f ? v : 0.01f * v; }

__device__ __forceinline__ uint32_t smem_u32(const void* p) {
    uint32_t a;
    asm("{ .reg .u64 t; cvta.to.shared.u64 t, %1; cvt.u32.u64 %0, t; }" : "=r"(a) : "l"(p));
    return a;
}
__device__ __forceinline__ void ldsm4(uint32_t* r, uint32_t a) {
    asm volatile("ldmatrix.sync.aligned.m8n8.x4.shared.b16 {%0,%1,%2,%3},[%4];"
        : "=r"(r[0]), "=r"(r[1]), "=r"(r[2]), "=r"(r[3]) : "r"(a));
}
__device__ __forceinline__ void ldsm4t(uint32_t* r, uint32_t a) {
    asm volatile("ldmatrix.sync.aligned.m8n8.x4.trans.shared.b16 {%0,%1,%2,%3},[%4];"
        : "=r"(r[0]), "=r"(r[1]), "=r"(r[2]), "=r"(r[3]) : "r"(a));
}
__device__ __forceinline__ void mma16(float* c, const uint32_t* a, uint32_t b0, uint32_t b1) {
    asm volatile("mma.sync.aligned.m16n8k16.row.col.f32.f16.f16.f32 "
        "{%0,%1,%2,%3},{%4,%5,%6,%7},{%8,%9},{%0,%1,%2,%3};"
        : "+f"(c[0]), "+f"(c[1]), "+f"(c[2]), "+f"(c[3])
        : "r"(a[0]), "r"(a[1]), "r"(a[2]), "r"(a[3]), "r"(b0), "r"(b1));
}
__device__ __forceinline__ void cpa16(uint32_t dst, const void* src) {
    asm volatile("cp.async.cg.shared.global [%0],[%1],16;" :: "r"(dst), "l"(src));
}
#define CP_COMMIT() asm volatile("cp.async.commit_group;" ::: "memory")
#define CP_WAIT0()  asm volatile("cp.async.wait_group 0;" ::: "memory")

__device__ __forceinline__ uint32_t h2(float a, float b) {
    __half2 v = __floats2half2_rn(a, b);
    return *reinterpret_cast<uint32_t*>(&v);
}

// ---------------------------------------------------------------------------
// prep: blocks 0..2047 = xcvt via register transpose (no smem, no sync),
//       blocks 2048..3071 = wgen (hypernet -> g_w fp16). 256 thr.
// ---------------------------------------------------------------------------
__global__ void prep_kernel(const float* __restrict__ x,
                            const float* __restrict__ h,
                            const float* __restrict__ fc_w, const float* __restrict__ fc_b,
                            const float* __restrict__ w1, const float* __restrict__ b1,
                            const float* __restrict__ w2, const float* __restrict__ b2,
                            const float* __restrict__ w3, const float* __restrict__ b3) {
    int bx = blockIdx.x, tid = threadIdx.x;

    if (bx < 2048) {
        // ------- xcvt: one (b, y) row, pure register transpose -------
        int yy = bx & 127, b = bx >> 7;
        int lane = tid & 31, w = tid >> 5;
        int c4 = lane >> 2, pq = lane & 3;
        int pxq = w * 16 + pq * 4;                 // 8 warps x 16 px = 128 px
        const float* xb = x + (((size_t)(b * 64 + c4 * 8)) * 128 + yy) * 128 + pxq;
        float4 v[8];
#pragma unroll
        for (int j = 0; j < 8; j++)
            v[j] = *reinterpret_cast<const float4*>(xb + (size_t)j * 16384);
        uint4* out = reinterpret_cast<uint4*>(
            g_xh + (((size_t)(b * 128 + yy)) * 128 + pxq) * 64 + c4 * 8);
        // pixel stride = 64 halfs = 8 uint4
#pragma unroll
        for (int k = 0; k < 4; k++) {
            float f0 = k == 0 ? v[0].x : k == 1 ? v[0].y : k == 2 ? v[0].z : v[0].w;
            float f1 = k == 0 ? v[1].x : k == 1 ? v[1].y : k == 2 ? v[1].z : v[1].w;
            float f2 = k == 0 ? v[2].x : k == 1 ? v[2].y : k == 2 ? v[2].z : v[2].w;
            float f3 = k == 0 ? v[3].x : k == 1 ? v[3].y : k == 2 ? v[3].z : v[3].w;
            float f4 = k == 0 ? v[4].x : k == 1 ? v[4].y : k == 2 ? v[4].z : v[4].w;
            float f5 = k == 0 ? v[5].x : k == 1 ? v[5].y : k == 2 ? v[5].z : v[5].w;
            float f6 = k == 0 ? v[6].x : k == 1 ? v[6].y : k == 2 ? v[6].z : v[6].w;
            float f7 = k == 0 ? v[7].x : k == 1 ? v[7].y : k == 2 ? v[7].z : v[7].w;
            out[(size_t)k * 8] = make_uint4(h2(f0, f1), h2(f2, f3), h2(f4, f5), h2(f6, f7));
        }
    } else {
        // ------- wgen: one (co, b) -------
        __shared__ float sbuf[2768];
        int j = bx - 2048;
        int co = j & 63, b = j >> 6;
        float* k1 = sbuf;            // 144
        float* k2 = sbuf + 144;      // 288
        float* k3 = sbuf + 432;      // 288
        float* w3s = sbuf + 720;     // 2048

        if (tid < 144) {
            float s = fc_b[tid];
#pragma unroll
            for (int q = 0; q < 8; q++) s += h[b * 8 + q] * fc_w[tid * 8 + q];
            k1[tid] = lrelu(s);
        }
        __syncthreads();
        for (int i = tid; i < 288; i += 256) {
            int o = i / 9, t = i % 9;
            float s = b1[o];
#pragma unroll
            for (int c = 0; c < 16; c++) s += w1[o * 16 + c] * k1[c * 9 + t];
            k2[i] = lrelu(s);
        }
        __syncthreads();
        for (int i = tid; i < 288; i += 256) {
            int o = i / 9, t = i % 9;
            float s = b2[o];
#pragma unroll
            for (int c = 0; c < 32; c++) s += w2[o * 32 + c] * k2[c * 9 + t];
            k3[i] = lrelu(s);
        }
        for (int i = tid; i < 2048; i += 256) w3s[i] = w3[(co * 64) * 32 + i];
        __syncthreads();

        for (int e = tid; e < 576; e += 256) {
            int ci = e / 9, t = e % 9;
            float s = b3[co * 64 + ci];
#pragma unroll
            for (int c = 0; c < 32; c++) s += w3s[ci * 32 + c] * k3[c * 9 + t];
            g_w[(size_t)(b * 9 + t) * 4608 + (size_t)ci * 72 + co] = __float2half(s);
        }
    }
}

// ---------------------------------------------------------------------------
// conv: implicit GEMM via mma.sync fp16 (single term). grid (64 row-pairs, 16 b),
// 256 thr, 2 CTAs/SM. A staged via cp.async from pre-converted g_xh.
// (identical to the proven 55.9us R11 kernel)
// ---------------------------------------------------------------------------
__global__ void __launch_bounds__(256, 2)
conv_kernel(const float* __restrict__ bias, float* __restrict__ y) {
    extern __shared__ char smem[];
    uint32_t xs_sh = smem_u32(smem);
    uint32_t bs_sh = xs_sh + BS_OFF;
    int tid = threadIdx.x, lane = tid & 31, wid = tid >> 5;
    int y0 = blockIdx.x * 2, b = blockIdx.y;

    // B tap0 cp.async (576 x 16B)
    {
        const char* g0 = (const char*)(g_w + (size_t)(b * 9) * 4608);
        for (int i = tid; i < 576; i += 256) cpa16(bs_sh + i * 16, g0 + i * 16);
    }
    // A cp.async: 4 rows (y0-1..y0+2) x 128 px x 8 chunks
    for (int i = tid; i < 4096; i += 256) {
        int sl = i >> 10, px = (i >> 3) & 127, ck = i & 7;
        int yy = y0 - 1 + sl;
        if ((unsigned)yy > 127u) continue;
        const char* src = (const char*)(g_xh + (((size_t)(b * 128 + yy)) * 128 + px) * 64) + ck * 16;
        cpa16(xs_sh + sl * ASLOT + (px + 1) * APITCH + ck * 16, src);
    }
    CP_COMMIT();

    if (tid < 64) ((float*)(smem + BIAS_OFF))[tid] = bias[tid];
    // zero halo rows (px -1 and px 128) for all slots
    uint4 z4 = make_uint4(0, 0, 0, 0);
    if (tid < 72) {
        int sl = tid / 18, rr = (tid / 9) & 1, ck = tid % 9;
        *(uint4*)(smem + sl * ASLOT + (rr ? 129 * APITCH : 0) + ck * 16) = z4;
    }
    // zero invalid slots (edge row-pairs)
    if (y0 == 0)
        for (int i = tid; i < 1170; i += 256) *(uint4*)(smem + i * 16) = z4;
    if (y0 == 126)
        for (int i = tid; i < 1170; i += 256) *(uint4*)(smem + 3 * ASLOT + i * 16) = z4;

    CP_WAIT0();
    __syncthreads();

    int r = wid >> 2;                 // output row within pair
    int wpx = (wid & 3) * 32;         // warp's px base
    uint32_t lane_off = (uint32_t)((((lane >> 3) & 1) * 8 + (lane & 7)) * 144 + (lane >> 4) * 16);

    float acc[64];
#pragma unroll
    for (int i = 0; i < 64; i++) acc[i] = 0.f;

    for (int t = 0; t < 9; t++) {
        int buf = t & 1;
        if (t < 8) {
            const char* gt = (const char*)(g_w + (size_t)(b * 9 + t + 1) * 4608);
            uint32_t db = bs_sh + (buf ^ 1) * BBUF;
            for (int i = tid; i < 576; i += 256) cpa16(db + i * 16, gt + i * 16);
            CP_COMMIT();
        }
        int dy = t / 3 - 1, dx = t % 3 - 1;
        int slot = 1 + dy + r;
        uint32_t abase = xs_sh + slot * ASLOT + (uint32_t)(wpx + 1 + dx) * APITCH + lane_off;
        uint32_t bbase = bs_sh + buf * BBUF + lane_off;
#pragma unroll
        for (int kc = 0; kc < 4; kc++) {
            uint32_t a[2][4];
            ldsm4(a[0], abase + kc * 32);
            ldsm4(a[1], abase + kc * 32 + 2304);
            uint32_t bh[4][4];
#pragma unroll
            for (int np = 0; np < 4; np++)
                ldsm4t(bh[np], bbase + kc * 2304 + np * 32);
#pragma unroll
            for (int np = 0; np < 4; np++)
#pragma unroll
                for (int mt = 0; mt < 2; mt++) {
                    float* A0 = acc + ((mt * 4 + np) * 2 + 0) * 4;
                    float* A1 = acc + ((mt * 4 + np) * 2 + 1) * 4;
                    mma16(A0, a[mt], bh[np][0], bh[np][1]);
                    mma16(A1, a[mt], bh[np][2], bh[np][3]);
                }
        }
        if (t < 8) { CP_WAIT0(); __syncthreads(); }
    }

    // epilogue: regs -> smem transpose [co][px pitch132] -> coalesced STG
    __syncthreads();
    {
        float* dsm = (float*)(smem + (r ? 33792 : 0));
        int g = lane >> 2, tq = lane & 3;
#pragma unroll
        for (int mt = 0; mt < 2; mt++)
#pragma unroll
            for (int np = 0; np < 4; np++)
#pragma unroll
                for (int s = 0; s < 2; s++) {
                    float* a4 = acc + ((mt * 4 + np) * 2 + s) * 4;
                    int co = np * 16 + s * 8 + 2 * tq;
                    int px = wpx + mt * 16 + g;
                    dsm[co * 132 + px] = a4[0];
                    dsm[(co + 1) * 132 + px] = a4[1];
                    dsm[co * 132 + px + 8] = a4[2];
                    dsm[(co + 1) * 132 + px + 8] = a4[3];
                }
    }
    __syncthreads();
    for (int i = tid; i < 4096; i += 256) {
        int rr = i >> 11, co = (i >> 5) & 63, q = i & 31;
        float4 v = *(float4*)((float*)(smem + (rr ? 33792 : 0)) + co * 132 + q * 4);
        float bb = ((float*)(smem + BIAS_OFF))[co];
        v.x += bb; v.y += bb; v.z += bb; v.w += bb;
        *(float4*)(y + (((size_t)(b * 64 + co)) * 128 + y0 + rr) * 128 + q * 4) = v;
    }
}

// ---------------------------------------------------------------------------
extern "C" void kernel_launch(void* const* d_in, const int* in_sizes, int n_in,
                              void* d_out, int out_size) {
    const float* x    = (const float*)d_in[0];
    const float* h    = (const float*)d_in[1];
    const float* fc_w = (const float*)d_in[2];
    const float* fc_b = (const float*)d_in[3];
    const float* w1   = (const float*)d_in[4];
    const float* b1   = (const float*)d_in[5];
    const float* w2   = (const float*)d_in[6];
    const float* b2   = (const float*)d_in[7];
    const float* w3   = (const float*)d_in[8];
    const float* b3   = (const float*)d_in[9];
    const float* bias = (const float*)d_in[10];
    float* y = (float*)d_out;

    cudaFuncSetAttribute(conv_kernel, cudaFuncAttributeMaxDynamicSharedMemorySize,
                         SMEM_TOTAL);

    prep_kernel<<<3072, 256>>>(x, h, fc_w, fc_b, w1, b1, w2, b2, w3, b3);
    conv_kernel<<<dim3(64, 16), 256, SMEM_TOTAL>>>(bias, y);
}

// round 15
// speedup vs baseline: 1.4606x; 1.0193x over previous
#include <cuda_runtime.h>
#include <cuda_fp16.h>
#include <cstdint>

#define Bn 16

// A staging: [slot4][px row 0..129][ci 64, pitch 72 halfs = 144B]
#define APITCH 144
#define ASLOT  (130 * APITCH)          // 18720
#define A_TOTAL (4 * ASLOT)            // 74880
#define BS_OFF A_TOTAL                 // 74880
#define BBUF   9216                    // one tap: 64 ci x 144B
#define BIAS_OFF (BS_OFF + 4 * BBUF)   // 111744  (4-buffer ring)
#define SMEM_TOTAL (BIAS_OFF + 256)    // 112000  -> still 2 CTAs/SM

// weights: per (b,tap): [ci64][co pitch 72] fp16 = 4608 elems
__device__ __half g_w[Bn * 9 * 4608];
// x pre-converted: [b][y][px][ci64] fp16
__device__ __half g_xh[(size_t)Bn * 128 * 128 * 64];

__device__ __forceinline__ float lrelu(float v) { return v > 0.f ? v : 0.01f * v; }

__device__ __forceinline__ uint32_t smem_u32(const void* p) {
    uint32_t a;
    asm("{ .reg .u64 t; cvta.to.shared.u64 t, %1; cvt.u32.u64 %0, t; }" : "=r"(a) : "l"(p));
    return a;
}
__device__ __forceinline__ void ldsm4(uint32_t* r, uint32_t a) {
    asm volatile("ldmatrix.sync.aligned.m8n8.x4.shared.b16 {%0,%1,%2,%3},[%4];"
        : "=r"(r[0]), "=r"(r[1]), "=r"(r[2]), "=r"(r[3]) : "r"(a));
}
__device__ __forceinline__ void ldsm4t(uint32_t* r, uint32_t a) {
    asm volatile("ldmatrix.sync.aligned.m8n8.x4.trans.shared.b16 {%0,%1,%2,%3},[%4];"
        : "=r"(r[0]), "=r"(r[1]), "=r"(r[2]), "=r"(r[3]) : "r"(a));
}
__device__ __forceinline__ void mma16(float* c, const uint32_t* a, uint32_t b0, uint32_t b1) {
    asm volatile("mma.sync.aligned.m16n8k16.row.col.f32.f16.f16.f32 "
        "{%0,%1,%2,%3},{%4,%5,%6,%7},{%8,%9},{%0,%1,%2,%3};"
        : "+f"(c[0]), "+f"(c[1]), "+f"(c[2]), "+f"(c[3])
        : "r"(a[0]), "r"(a[1]), "r"(a[2]), "r"(a[3]), "r"(b0), "r"(b1));
}
__device__ __forceinline__ void cpa16(uint32_t dst, const void* src) {
    asm volatile("cp.async.cg.shared.global [%0],[%1],16;" :: "r"(dst), "l"(src));
}
#define CP_COMMIT() asm volatile("cp.async.commit_group;" ::: "memory")
#define CP_WAIT0()  asm volatile("cp.async.wait_group 0;" ::: "memory")

__device__ __forceinline__ uint32_t h2(float a, float b) {
    __half2 v = __floats2half2_rn(a, b);
    return *reinterpret_cast<uint32_t*>(&v);
}

// ---------------------------------------------------------------------------
// prep: blocks 0..2047 = xcvt via register transpose (no smem, no sync),
//       blocks 2048..3071 = wgen (hypernet -> g_w fp16). 256 thr.
// ---------------------------------------------------------------------------
__global__ void prep_kernel(const float* __restrict__ x,
                            const float* __restrict__ h,
                            const float* __restrict__ fc_w, const float* __restrict__ fc_b,
                            const float* __restrict__ w1, const float* __restrict__ b1,
                            const float* __restrict__ w2, const float* __restrict__ b2,
                            const float* __restrict__ w3, const float* __restrict__ b3) {
    int bx = blockIdx.x, tid = threadIdx.x;

    if (bx < 2048) {
        // ------- xcvt: one (b, y) row, pure register transpose -------
        int yy = bx & 127, b = bx >> 7;
        int lane = tid & 31, w = tid >> 5;
        int c4 = lane >> 2, pq = lane & 3;
        int pxq = w * 16 + pq * 4;                 // 8 warps x 16 px = 128 px
        const float* xb = x + (((size_t)(b * 64 + c4 * 8)) * 128 + yy) * 128 + pxq;
        float4 v[8];
#pragma unroll
        for (int j = 0; j < 8; j++)
            v[j] = *reinterpret_cast<const float4*>(xb + (size_t)j * 16384);
        uint4* out = reinterpret_cast<uint4*>(
            g_xh + (((size_t)(b * 128 + yy)) * 128 + pxq) * 64 + c4 * 8);
        // pixel stride = 64 halfs = 8 uint4
#pragma unroll
        for (int k = 0; k < 4; k++) {
            float f0 = k == 0 ? v[0].x : k == 1 ? v[0].y : k == 2 ? v[0].z : v[0].w;
            float f1 = k == 0 ? v[1].x : k == 1 ? v[1].y : k == 2 ? v[1].z : v[1].w;
            float f2 = k == 0 ? v[2].x : k == 1 ? v[2].y : k == 2 ? v[2].z : v[2].w;
            float f3 = k == 0 ? v[3].x : k == 1 ? v[3].y : k == 2 ? v[3].z : v[3].w;
            float f4 = k == 0 ? v[4].x : k == 1 ? v[4].y : k == 2 ? v[4].z : v[4].w;
            float f5 = k == 0 ? v[5].x : k == 1 ? v[5].y : k == 2 ? v[5].z : v[5].w;
            float f6 = k == 0 ? v[6].x : k == 1 ? v[6].y : k == 2 ? v[6].z : v[6].w;
            float f7 = k == 0 ? v[7].x : k == 1 ? v[7].y : k == 2 ? v[7].z : v[7].w;
            out[(size_t)k * 8] = make_uint4(h2(f0, f1), h2(f2, f3), h2(f4, f5), h2(f6, f7));
        }
    } else {
        // ------- wgen: one (co, b) -------
        __shared__ float sbuf[2768];
        int j = bx - 2048;
        int co = j & 63, b = j >> 6;
        float* k1 = sbuf;            // 144
        float* k2 = sbuf + 144;      // 288
        float* k3 = sbuf + 432;      // 288
        float* w3s = sbuf + 720;     // 2048

        if (tid < 144) {
            float s = fc_b[tid];
#pragma unroll
            for (int q = 0; q < 8; q++) s += h[b * 8 + q] * fc_w[tid * 8 + q];
            k1[tid] = lrelu(s);
        }
        __syncthreads();
        for (int i = tid; i < 288; i += 256) {
            int o = i / 9, t = i % 9;
            float s = b1[o];
#pragma unroll
            for (int c = 0; c < 16; c++) s += w1[o * 16 + c] * k1[c * 9 + t];
            k2[i] = lrelu(s);
        }
        __syncthreads();
        for (int i = tid; i < 288; i += 256) {
            int o = i / 9, t = i % 9;
            float s = b2[o];
#pragma unroll
            for (int c = 0; c < 32; c++) s += w2[o * 32 + c] * k2[c * 9 + t];
            k3[i] = lrelu(s);
        }
        for (int i = tid; i < 2048; i += 256) w3s[i] = w3[(co * 64) * 32 + i];
        __syncthreads();

        for (int e = tid; e < 576; e += 256) {
            int ci = e / 9, t = e % 9;
            float s = b3[co * 64 + ci];
#pragma unroll
            for (int c = 0; c < 32; c++) s += w3s[ci * 32 + c] * k3[c * 9 + t];
            g_w[(size_t)(b * 9 + t) * 4608 + (size_t)ci * 72 + co] = __float2half(s);
        }
    }
}

// ---------------------------------------------------------------------------
// conv: implicit GEMM via mma.sync fp16. grid (64 row-pairs, 16 b), 256 thr,
// 2 CTAs/SM. B streamed through a 4-buffer ring; block barrier every 2 taps
// (wait -> barrier -> issue pattern).
// ---------------------------------------------------------------------------
__global__ void __launch_bounds__(256, 2)
conv_kernel(const float* __restrict__ bias, float* __restrict__ y) {
    extern __shared__ char smem[];
    uint32_t xs_sh = smem_u32(smem);
    uint32_t bs_sh = xs_sh + BS_OFF;
    int tid = threadIdx.x, lane = tid & 31, wid = tid >> 5;
    int y0 = blockIdx.x * 2, b = blockIdx.y;

    // group G0: B0 + B1 + A
    for (int tt = 0; tt < 2; tt++) {
        const char* g0 = (const char*)(g_w + (size_t)(b * 9 + tt) * 4608);
        uint32_t db = bs_sh + tt * BBUF;
        for (int i = tid; i < 576; i += 256) cpa16(db + i * 16, g0 + i * 16);
    }
    // A cp.async: 4 rows (y0-1..y0+2) x 128 px x 8 chunks
    for (int i = tid; i < 4096; i += 256) {
        int sl = i >> 10, px = (i >> 3) & 127, ck = i & 7;
        int yy = y0 - 1 + sl;
        if ((unsigned)yy > 127u) continue;
        const char* src = (const char*)(g_xh + (((size_t)(b * 128 + yy)) * 128 + px) * 64) + ck * 16;
        cpa16(xs_sh + sl * ASLOT + (px + 1) * APITCH + ck * 16, src);
    }
    CP_COMMIT();

    if (tid < 64) ((float*)(smem + BIAS_OFF))[tid] = bias[tid];
    // zero halo rows (px -1 and px 128) for all slots
    uint4 z4 = make_uint4(0, 0, 0, 0);
    if (tid < 72) {
        int sl = tid / 18, rr = (tid / 9) & 1, ck = tid % 9;
        *(uint4*)(smem + sl * ASLOT + (rr ? 129 * APITCH : 0) + ck * 16) = z4;
    }
    // zero invalid slots (edge row-pairs)
    if (y0 == 0)
        for (int i = tid; i < 1170; i += 256) *(uint4*)(smem + i * 16) = z4;
    if (y0 == 126)
        for (int i = tid; i < 1170; i += 256) *(uint4*)(smem + 3 * ASLOT + i * 16) = z4;

    CP_WAIT0();
    __syncthreads();

    // issue B2, B3 (group G1) — buffers 2,3 untouched so far
    for (int tt = 2; tt < 4; tt++) {
        const char* gt = (const char*)(g_w + (size_t)(b * 9 + tt) * 4608);
        uint32_t db = bs_sh + tt * BBUF;
        for (int i = tid; i < 576; i += 256) cpa16(db + i * 16, gt + i * 16);
    }
    CP_COMMIT();

    int r = wid >> 2;                 // output row within pair
    int wpx = (wid & 3) * 32;         // warp's px base
    uint32_t lane_off = (uint32_t)((((lane >> 3) & 1) * 8 + (lane & 7)) * 144 + (lane >> 4) * 16);

    float acc[64];
#pragma unroll
    for (int i = 0; i < 64; i++) acc[i] = 0.f;

    for (int t = 0; t < 9; t++) {
        int dy = t / 3 - 1, dx = t % 3 - 1;
        int slot = 1 + dy + r;
        uint32_t abase = xs_sh + slot * ASLOT + (uint32_t)(wpx + 1 + dx) * APITCH + lane_off;
        uint32_t bbase = bs_sh + (uint32_t)(t & 3) * BBUF + lane_off;
#pragma unroll
        for (int kc = 0; kc < 4; kc++) {
            uint32_t a[2][4];
            ldsm4(a[0], abase + kc * 32);
            ldsm4(a[1], abase + kc * 32 + 2304);
            uint32_t bh[4][4];
#pragma unroll
            for (int np = 0; np < 4; np++)
                ldsm4t(bh[np], bbase + kc * 2304 + np * 32);
#pragma unroll
            for (int np = 0; np < 4; np++)
#pragma unroll
                for (int mt = 0; mt < 2; mt++) {
                    float* A0 = acc + ((mt * 4 + np) * 2 + 0) * 4;
                    float* A1 = acc + ((mt * 4 + np) * 2 + 1) * 4;
                    mma16(A0, a[mt], bh[np][0], bh[np][1]);
                    mma16(A1, a[mt], bh[np][2], bh[np][3]);
                }
        }
        // sync point after odd taps: wait pending group -> barrier -> issue next 2
        if ((t & 1) == 1 && t < 8) {
            CP_WAIT0();
            __syncthreads();
            int t3 = t + 3, t4 = t + 4;
            if (t3 <= 8) {
                const char* gt = (const char*)(g_w + (size_t)(b * 9 + t3) * 4608);
                uint32_t db = bs_sh + (uint32_t)(t3 & 3) * BBUF;
                for (int i = tid; i < 576; i += 256) cpa16(db + i * 16, gt + i * 16);
            }
            if (t4 <= 8) {
                const char* gt = (const char*)(g_w + (size_t)(b * 9 + t4) * 4608);
                uint32_t db = bs_sh + (uint32_t)(t4 & 3) * BBUF;
                for (int i = tid; i < 576; i += 256) cpa16(db + i * 16, gt + i * 16);
            }
            CP_COMMIT();
        }
    }

    // epilogue: regs -> smem transpose [co][px pitch132] -> coalesced STG
    __syncthreads();
    {
        float* dsm = (float*)(smem + (r ? 33792 : 0));
        int g = lane >> 2, tq = lane & 3;
#pragma unroll
        for (int mt = 0; mt < 2; mt++)
#pragma unroll
            for (int np = 0; np < 4; np++)
#pragma unroll
                for (int s = 0; s < 2; s++) {
                    float* a4 = acc + ((mt * 4 + np) * 2 + s) * 4;
                    int co = np * 16 + s * 8 + 2 * tq;
                    int px = wpx + mt * 16 + g;
                    dsm[co * 132 + px] = a4[0];
                    dsm[(co + 1) * 132 + px] = a4[1];
                    dsm[co * 132 + px + 8] = a4[2];
                    dsm[(co + 1) * 132 + px + 8] = a4[3];
                }
    }
    __syncthreads();
    for (int i = tid; i < 4096; i += 256) {
        int rr = i >> 11, co = (i >> 5) & 63, q = i & 31;
        float4 v = *(float4*)((float*)(smem + (rr ? 33792 : 0)) + co * 132 + q * 4);
        float bb = ((float*)(smem + BIAS_OFF))[co];
        v.x += bb; v.y += bb; v.z += bb; v.w += bb;
        *(float4*)(y + (((size_t)(b * 64 + co)) * 128 + y0 + rr) * 128 + q * 4) = v;
    }
}

// ---------------------------------------------------------------------------
extern "C" void kernel_launch(void* const* d_in, const int* in_sizes, int n_in,
                              void* d_out, int out_size) {
    const float* x    = (const float*)d_in[0];
    const float* h    = (const float*)d_in[1];
    const float* fc_w = (const float*)d_in[2];
    const float* fc_b = (const float*)d_in[3];
    const float* w1   = (const float*)d_in[4];
    const float* b1   = (const float*)d_in[5];
    const float* w2   = (const float*)d_in[6];
    const float* b2   = (const float*)d_in[7];
    const float* w3   = (const float*)d_in[8];
    const float* b3   = (const float*)d_in[9];
    const float* bias = (const float*)d_in[10];
    float* y = (float*)d_out;

    cudaFuncSetAttribute(conv_kernel, cudaFuncAttributeMaxDynamicSharedMemorySize,
                         SMEM_TOTAL);

    prep_kernel<<<3072, 256>>>(x, h, fc_w, fc_b, w1, b1, w2, b2, w3, b3);
    conv_kernel<<<dim3(64, 16), 256, SMEM_TOTAL>>>(bias, y);
}

// round 16
// speedup vs baseline: 1.4712x; 1.0073x over previous
#include <cuda_runtime.h>
#include <cuda_fp16.h>
#include <cstdint>

#define Bn 16

// A staging: [slot4][px row 0..129][ci 64, pitch 72 halfs = 144B]
#define APITCH 144
#define ASLOT  (130 * APITCH)          // 18720
#define A_TOTAL (4 * ASLOT)            // 74880
#define BS_OFF A_TOTAL                 // 74880
#define BBUF   9216                    // one tap: 64 ci x 144B
#define BIAS_OFF (BS_OFF + 4 * BBUF)   // 111744  (4-buffer ring)
#define SMEM_TOTAL (BIAS_OFF + 256)    // 112000  -> still 2 CTAs/SM

// weights: per (b,tap): [ci64][co pitch 72] fp16 = 4608 elems
__device__ __half g_w[Bn * 9 * 4608];
// x pre-converted: [b][y][px][ci64] fp16
__device__ __half g_xh[(size_t)Bn * 128 * 128 * 64];

__device__ __forceinline__ float lrelu(float v) { return v > 0.f ? v : 0.01f * v; }

__device__ __forceinline__ uint32_t smem_u32(const void* p) {
    uint32_t a;
    asm("{ .reg .u64 t; cvta.to.shared.u64 t, %1; cvt.u32.u64 %0, t; }" : "=r"(a) : "l"(p));
    return a;
}
__device__ __forceinline__ void ldsm4(uint32_t* r, uint32_t a) {
    asm volatile("ldmatrix.sync.aligned.m8n8.x4.shared.b16 {%0,%1,%2,%3},[%4];"
        : "=r"(r[0]), "=r"(r[1]), "=r"(r[2]), "=r"(r[3]) : "r"(a));
}
__device__ __forceinline__ void ldsm4t(uint32_t* r, uint32_t a) {
    asm volatile("ldmatrix.sync.aligned.m8n8.x4.trans.shared.b16 {%0,%1,%2,%3},[%4];"
        : "=r"(r[0]), "=r"(r[1]), "=r"(r[2]), "=r"(r[3]) : "r"(a));
}
__device__ __forceinline__ void mma16(float* c, const uint32_t* a, uint32_t b0, uint32_t b1) {
    asm volatile("mma.sync.aligned.m16n8k16.row.col.f32.f16.f16.f32 "
        "{%0,%1,%2,%3},{%4,%5,%6,%7},{%8,%9},{%0,%1,%2,%3};"
        : "+f"(c[0]), "+f"(c[1]), "+f"(c[2]), "+f"(c[3])
        : "r"(a[0]), "r"(a[1]), "r"(a[2]), "r"(a[3]), "r"(b0), "r"(b1));
}
__device__ __forceinline__ void cpa16(uint32_t dst, const void* src) {
    asm volatile("cp.async.cg.shared.global [%0],[%1],16;" :: "r"(dst), "l"(src));
}
#define CP_COMMIT() asm volatile("cp.async.commit_group;" ::: "memory")
#define CP_WAIT0()  asm volatile("cp.async.wait_group 0;" ::: "memory")

__device__ __forceinline__ uint32_t h2(float a, float b) {
    __half2 v = __floats2half2_rn(a, b);
    return *reinterpret_cast<uint32_t*>(&v);
}

// ---------------------------------------------------------------------------
// prep: blocks 0..1023 = wgen (LONG, launched first so they overlap the
//       stream of short xcvt blocks), blocks 1024..3071 = xcvt (register
//       transpose, no smem, no sync). 256 thr.
// ---------------------------------------------------------------------------
__global__ void prep_kernel(const float* __restrict__ x,
                            const float* __restrict__ h,
                            const float* __restrict__ fc_w, const float* __restrict__ fc_b,
                            const float* __restrict__ w1, const float* __restrict__ b1,
                            const float* __restrict__ w2, const float* __restrict__ b2,
                            const float* __restrict__ w3, const float* __restrict__ b3) {
    int bx = blockIdx.x, tid = threadIdx.x;

    if (bx >= 1024) {
        // ------- xcvt: one (b, y) row, pure register transpose -------
        int j = bx - 1024;
        int yy = j & 127, b = j >> 7;
        int lane = tid & 31, w = tid >> 5;
        int c4 = lane >> 2, pq = lane & 3;
        int pxq = w * 16 + pq * 4;                 // 8 warps x 16 px = 128 px
        const float* xb = x + (((size_t)(b * 64 + c4 * 8)) * 128 + yy) * 128 + pxq;
        float4 v[8];
#pragma unroll
        for (int j2 = 0; j2 < 8; j2++)
            v[j2] = *reinterpret_cast<const float4*>(xb + (size_t)j2 * 16384);
        uint4* out = reinterpret_cast<uint4*>(
            g_xh + (((size_t)(b * 128 + yy)) * 128 + pxq) * 64 + c4 * 8);
        // pixel stride = 64 halfs = 8 uint4
#pragma unroll
        for (int k = 0; k < 4; k++) {
            float f0 = k == 0 ? v[0].x : k == 1 ? v[0].y : k == 2 ? v[0].z : v[0].w;
            float f1 = k == 0 ? v[1].x : k == 1 ? v[1].y : k == 2 ? v[1].z : v[1].w;
            float f2 = k == 0 ? v[2].x : k == 1 ? v[2].y : k == 2 ? v[2].z : v[2].w;
            float f3 = k == 0 ? v[3].x : k == 1 ? v[3].y : k == 2 ? v[3].z : v[3].w;
            float f4 = k == 0 ? v[4].x : k == 1 ? v[4].y : k == 2 ? v[4].z : v[4].w;
            float f5 = k == 0 ? v[5].x : k == 1 ? v[5].y : k == 2 ? v[5].z : v[5].w;
            float f6 = k == 0 ? v[6].x : k == 1 ? v[6].y : k == 2 ? v[6].z : v[6].w;
            float f7 = k == 0 ? v[7].x : k == 1 ? v[7].y : k == 2 ? v[7].z : v[7].w;
            out[(size_t)k * 8] = make_uint4(h2(f0, f1), h2(f2, f3), h2(f4, f5), h2(f6, f7));
        }
    } else {
        // ------- wgen: one (co, b) -------
        __shared__ float sbuf[2768];
        int co = bx & 63, b = bx >> 6;
        float* k1 = sbuf;            // 144
        float* k2 = sbuf + 144;      // 288
        float* k3 = sbuf + 432;      // 288
        float* w3s = sbuf + 720;     // 2048

        if (tid < 144) {
            float s = fc_b[tid];
#pragma unroll
            for (int q = 0; q < 8; q++) s += h[b * 8 + q] * fc_w[tid * 8 + q];
            k1[tid] = lrelu(s);
        }
        __syncthreads();
        for (int i = tid; i < 288; i += 256) {
            int o = i / 9, t = i % 9;
            float s = b1[o];
#pragma unroll
            for (int c = 0; c < 16; c++) s += w1[o * 16 + c] * k1[c * 9 + t];
            k2[i] = lrelu(s);
        }
        __syncthreads();
        for (int i = tid; i < 288; i += 256) {
            int o = i / 9, t = i % 9;
            float s = b2[o];
#pragma unroll
            for (int c = 0; c < 32; c++) s += w2[o * 32 + c] * k2[c * 9 + t];
            k3[i] = lrelu(s);
        }
        for (int i = tid; i < 2048; i += 256) w3s[i] = w3[(co * 64) * 32 + i];
        __syncthreads();

        for (int e = tid; e < 576; e += 256) {
            int ci = e / 9, t = e % 9;
            float s = b3[co * 64 + ci];
#pragma unroll
            for (int c = 0; c < 32; c++) s += w3s[ci * 32 + c] * k3[c * 9 + t];
            g_w[(size_t)(b * 9 + t) * 4608 + (size_t)ci * 72 + co] = __float2half(s);
        }
    }
}

// ---------------------------------------------------------------------------
// conv: implicit GEMM via mma.sync fp16. grid (64 row-pairs, 16 b), 256 thr,
// 2 CTAs/SM. B streamed through a 4-buffer ring; block barrier every 2 taps
// (wait -> barrier -> issue pattern). (identical to proven 55.8us R15 conv)
// ---------------------------------------------------------------------------
__global__ void __launch_bounds__(256, 2)
conv_kernel(const float* __restrict__ bias, float* __restrict__ y) {
    extern __shared__ char smem[];
    uint32_t xs_sh = smem_u32(smem);
    uint32_t bs_sh = xs_sh + BS_OFF;
    int tid = threadIdx.x, lane = tid & 31, wid = tid >> 5;
    int y0 = blockIdx.x * 2, b = blockIdx.y;

    // group G0: B0 + B1 + A
    for (int tt = 0; tt < 2; tt++) {
        const char* g0 = (const char*)(g_w + (size_t)(b * 9 + tt) * 4608);
        uint32_t db = bs_sh + tt * BBUF;
        for (int i = tid; i < 576; i += 256) cpa16(db + i * 16, g0 + i * 16);
    }
    // A cp.async: 4 rows (y0-1..y0+2) x 128 px x 8 chunks
    for (int i = tid; i < 4096; i += 256) {
        int sl = i >> 10, px = (i >> 3) & 127, ck = i & 7;
        int yy = y0 - 1 + sl;
        if ((unsigned)yy > 127u) continue;
        const char* src = (const char*)(g_xh + (((size_t)(b * 128 + yy)) * 128 + px) * 64) + ck * 16;
        cpa16(xs_sh + sl * ASLOT + (px + 1) * APITCH + ck * 16, src);
    }
    CP_COMMIT();

    if (tid < 64) ((float*)(smem + BIAS_OFF))[tid] = bias[tid];
    // zero halo rows (px -1 and px 128) for all slots
    uint4 z4 = make_uint4(0, 0, 0, 0);
    if (tid < 72) {
        int sl = tid / 18, rr = (tid / 9) & 1, ck = tid % 9;
        *(uint4*)(smem + sl * ASLOT + (rr ? 129 * APITCH : 0) + ck * 16) = z4;
    }
    // zero invalid slots (edge row-pairs)
    if (y0 == 0)
        for (int i = tid; i < 1170; i += 256) *(uint4*)(smem + i * 16) = z4;
    if (y0 == 126)
        for (int i = tid; i < 1170; i += 256) *(uint4*)(smem + 3 * ASLOT + i * 16) = z4;

    CP_WAIT0();
    __syncthreads();

    // issue B2, B3 (group G1) — buffers 2,3 untouched so far
    for (int tt = 2; tt < 4; tt++) {
        const char* gt = (const char*)(g_w + (size_t)(b * 9 + tt) * 4608);
        uint32_t db = bs_sh + tt * BBUF;
        for (int i = tid; i < 576; i += 256) cpa16(db + i * 16, gt + i * 16);
    }
    CP_COMMIT();

    int r = wid >> 2;                 // output row within pair
    int wpx = (wid & 3) * 32;         // warp's px base
    uint32_t lane_off = (uint32_t)((((lane >> 3) & 1) * 8 + (lane & 7)) * 144 + (lane >> 4) * 16);

    float acc[64];
#pragma unroll
    for (int i = 0; i < 64; i++) acc[i] = 0.f;

    for (int t = 0; t < 9; t++) {
        int dy = t / 3 - 1, dx = t % 3 - 1;
        int slot = 1 + dy + r;
        uint32_t abase = xs_sh + slot * ASLOT + (uint32_t)(wpx + 1 + dx) * APITCH + lane_off;
        uint32_t bbase = bs_sh + (uint32_t)(t & 3) * BBUF + lane_off;
#pragma unroll
        for (int kc = 0; kc < 4; kc++) {
            uint32_t a[2][4];
            ldsm4(a[0], abase + kc * 32);
            ldsm4(a[1], abase + kc * 32 + 2304);
            uint32_t bh[4][4];
#pragma unroll
            for (int np = 0; np < 4; np++)
                ldsm4t(bh[np], bbase + kc * 2304 + np * 32);
#pragma unroll
            for (int np = 0; np < 4; np++)
#pragma unroll
                for (int mt = 0; mt < 2; mt++) {
                    float* A0 = acc + ((mt * 4 + np) * 2 + 0) * 4;
                    float* A1 = acc + ((mt * 4 + np) * 2 + 1) * 4;
                    mma16(A0, a[mt], bh[np][0], bh[np][1]);
                    mma16(A1, a[mt], bh[np][2], bh[np][3]);
                }
        }
        // sync point after odd taps: wait pending group -> barrier -> issue next 2
        if ((t & 1) == 1 && t < 8) {
            CP_WAIT0();
            __syncthreads();
            int t3 = t + 3, t4 = t + 4;
            if (t3 <= 8) {
                const char* gt = (const char*)(g_w + (size_t)(b * 9 + t3) * 4608);
                uint32_t db = bs_sh + (uint32_t)(t3 & 3) * BBUF;
                for (int i = tid; i < 576; i += 256) cpa16(db + i * 16, gt + i * 16);
            }
            if (t4 <= 8) {
                const char* gt = (const char*)(g_w + (size_t)(b * 9 + t4) * 4608);
                uint32_t db = bs_sh + (uint32_t)(t4 & 3) * BBUF;
                for (int i = tid; i < 576; i += 256) cpa16(db + i * 16, gt + i * 16);
            }
            CP_COMMIT();
        }
    }

    // epilogue: regs -> smem transpose [co][px pitch132] -> coalesced STG
    __syncthreads();
    {
        float* dsm = (float*)(smem + (r ? 33792 : 0));
        int g = lane >> 2, tq = lane & 3;
#pragma unroll
        for (int mt = 0; mt < 2; mt++)
#pragma unroll
            for (int np = 0; np < 4; np++)
#pragma unroll
                for (int s = 0; s < 2; s++) {
                    float* a4 = acc + ((mt * 4 + np) * 2 + s) * 4;
                    int co = np * 16 + s * 8 + 2 * tq;
                    int px = wpx + mt * 16 + g;
                    dsm[co * 132 + px] = a4[0];
                    dsm[(co + 1) * 132 + px] = a4[1];
                    dsm[co * 132 + px + 8] = a4[2];
                    dsm[(co + 1) * 132 + px + 8] = a4[3];
                }
    }
    __syncthreads();
    for (int i = tid; i < 4096; i += 256) {
        int rr = i >> 11, co = (i >> 5) & 63, q = i & 31;
        float4 v = *(float4*)((float*)(smem + (rr ? 33792 : 0)) + co * 132 + q * 4);
        float bb = ((float*)(smem + BIAS_OFF))[co];
        v.x += bb; v.y += bb; v.z += bb; v.w += bb;
        *(float4*)(y + (((size_t)(b * 64 + co)) * 128 + y0 + rr) * 128 + q * 4) = v;
    }
}

// ---------------------------------------------------------------------------
extern "C" void kernel_launch(void* const* d_in, const int* in_sizes, int n_in,
                              void* d_out, int out_size) {
    const float* x    = (const float*)d_in[0];
    const float* h    = (const float*)d_in[1];
    const float* fc_w = (const float*)d_in[2];
    const float* fc_b = (const float*)d_in[3];
    const float* w1   = (const float*)d_in[4];
    const float* b1   = (const float*)d_in[5];
    const float* w2   = (const float*)d_in[6];
    const float* b2   = (const float*)d_in[7];
    const float* w3   = (const float*)d_in[8];
    const float* b3   = (const float*)d_in[9];
    const float* bias = (const float*)d_in[10];
    float* y = (float*)d_out;

    cudaFuncSetAttribute(conv_kernel, cudaFuncAttributeMaxDynamicSharedMemorySize,
                         SMEM_TOTAL);

    prep_kernel<<<3072, 256>>>(x, h, fc_w, fc_b, w1, b1, w2, b2, w3, b3);
    conv_kernel<<<dim3(64, 16), 256, SMEM_TOTAL>>>(bias, y);
}